// round 3
// baseline (speedup 1.0000x reference)
#include <cuda_runtime.h>
#include <cuda_bf16.h>
#include <cstdint>

#define NN 50000
#define NE 800000
#define NG 64
#define NF 11
#define EF 14
#define HH 128
#define PP 128
#define NL 3
#define BN_EPS 1e-5f

// ---------------- scratch (__device__ globals; referenced ONLY in device code)
__device__ float g_h[NN * HH];                 // node features
__device__ float g_z[NN * HH];                 // h + agg
__device__ float g_t[NN * HH];                 // MLP intermediate
__device__ float g_eacsr[(size_t)NE * EF];     // edge_attr permuted to CSR order
__device__ int   g_cnt[NN];
__device__ int   g_row[NN + 1];
__device__ int   g_cur[NN];
__device__ int   g_src[NE];
__device__ float g_scale[NL * HH];
__device__ float g_shift[NL * HH];
__device__ float g_pool[NG * HH];
__device__ float g_gcnt[NG];

// ---------------- zero scratch ----------------------------------------------
__global__ void __launch_bounds__(256) zero_kernel() {
    int i = blockIdx.x * blockDim.x + threadIdx.x;
    if (i < NN) g_cnt[i] = 0;
    if (i < NG * HH) g_pool[i] = 0.f;
    if (i < NG) g_gcnt[i] = 0.f;
}

// ---------------- fold BN params --------------------------------------------
__global__ void __launch_bounds__(128) prep_kernel(const float* __restrict__ lin1_b,
                                                   const float* __restrict__ gamma,
                                                   const float* __restrict__ beta,
                                                   const float* __restrict__ mean,
                                                   const float* __restrict__ var) {
    int i = blockIdx.x * blockDim.x + threadIdx.x;
    if (i < NL * HH) {
        float sc = gamma[i] * rsqrtf(var[i] + BN_EPS);
        g_scale[i] = sc;
        g_shift[i] = (lin1_b[i] - mean[i]) * sc + beta[i];
    }
}

// ---------------- node embedding: h = x @ node_W^T + node_b -----------------
__global__ void __launch_bounds__(128) node_embed(const float* __restrict__ x,
                                                  const float* __restrict__ W,
                                                  const float* __restrict__ b) {
    __shared__ float xs[32 * NF];
    int t = threadIdx.x;            // 128 threads, one output column each
    float w[NF];
#pragma unroll
    for (int k = 0; k < NF; k++) w[k] = W[t * NF + k];
    float bias = b[t];
    int base = blockIdx.x * 32;
    for (int i = t; i < 32 * NF; i += 128) {
        int node = base + i / NF;
        xs[i] = (node < NN) ? x[node * NF + i % NF] : 0.f;
    }
    __syncthreads();
    for (int j = 0; j < 32; j++) {
        int node = base + j;
        if (node >= NN) break;
        float acc = bias;
#pragma unroll
        for (int k = 0; k < NF; k++) acc = fmaf(xs[j * NF + k], w[k], acc);
        g_h[node * HH + t] = acc;
    }
}

// ---------------- CSR build --------------------------------------------------
__global__ void __launch_bounds__(256) hist_kernel(const int* __restrict__ ei) {
    int i = blockIdx.x * blockDim.x + threadIdx.x;
    if (i < NE) atomicAdd(&g_cnt[ei[NE + i]], 1);   // dst = ei[1][i]
}

__global__ void __launch_bounds__(1024) scan_kernel() {
    __shared__ int partial[1024];
    const int CH = (NN + 1023) / 1024;   // 49
    int t = threadIdx.x;
    int beg = t * CH;
    int sum = 0;
    for (int i = 0; i < CH; i++) {
        int idx = beg + i;
        if (idx < NN) sum += g_cnt[idx];
    }
    partial[t] = sum;
    __syncthreads();
    for (int off = 1; off < 1024; off <<= 1) {
        int v = (t >= off) ? partial[t - off] : 0;
        __syncthreads();
        partial[t] += v;
        __syncthreads();
    }
    int run = (t > 0) ? partial[t - 1] : 0;
    for (int i = 0; i < CH; i++) {
        int idx = beg + i;
        if (idx < NN) {
            g_row[idx] = run;
            g_cur[idx] = run;
            run += g_cnt[idx];
        }
    }
    if (t == 1023) g_row[NN] = run;
}

// scatter: assign CSR slot, record src, permute edge_attr into CSR order
__global__ void __launch_bounds__(256) scatter_kernel(const int* __restrict__ ei,
                                                      const float* __restrict__ ea) {
    int i = blockIdx.x * blockDim.x + threadIdx.x;
    if (i < NE) {
        int d = ei[NE + i];
        int p = atomicAdd(&g_cur[d], 1);
        g_src[p] = ei[i];
        const float* s = ea + (size_t)i * EF;
        float* o = g_eacsr + (size_t)p * EF;
#pragma unroll
        for (int k = 0; k < EF; k++) o[k] = s[k];
    }
}

// ---------------- GINE aggregation: z = h + sum relu(h[src] + e_ij) ---------
// warp per node; lane owns 4 features; edge embedding recomputed on the fly.
__global__ void __launch_bounds__(256) aggregate_kernel(const float* __restrict__ eW,
                                                        const float* __restrict__ eB) {
    int gid = blockIdx.x * blockDim.x + threadIdx.x;
    int node = gid >> 5;
    if (node >= NN) return;
    int lane = gid & 31;

    // lane's 4 rows of edge_W + bias
    float w[4][EF];
    float eb[4];
#pragma unroll
    for (int c = 0; c < 4; c++) {
        eb[c] = eB[4 * lane + c];
#pragma unroll
        for (int k = 0; k < EF; k++) w[c][k] = eW[(4 * lane + c) * EF + k];
    }

    const float4* hp = (const float4*)g_h;
    float4 acc = make_float4(0.f, 0.f, 0.f, 0.f);
    int beg = g_row[node], end = g_row[node + 1];
    for (int i = beg; i < end; i++) {
        int s = __ldg(&g_src[i]);
        float av = (lane < EF) ? __ldg(&g_eacsr[(size_t)i * EF + lane]) : 0.f;
        float4 hv = hp[s * 32 + lane];
        float m0 = eb[0], m1 = eb[1], m2 = eb[2], m3 = eb[3];
#pragma unroll
        for (int k = 0; k < EF; k++) {
            float ek = __shfl_sync(0xffffffffu, av, k);
            m0 = fmaf(w[0][k], ek, m0);
            m1 = fmaf(w[1][k], ek, m1);
            m2 = fmaf(w[2][k], ek, m2);
            m3 = fmaf(w[3][k], ek, m3);
        }
        acc.x += fmaxf(hv.x + m0, 0.f);
        acc.y += fmaxf(hv.y + m1, 0.f);
        acc.z += fmaxf(hv.z + m2, 0.f);
        acc.w += fmaxf(hv.w + m3, 0.f);
    }
    float4 hv = hp[node * 32 + lane];
    acc.x += hv.x; acc.y += hv.y; acc.z += hv.z; acc.w += hv.w;
    ((float4*)g_z)[node * 32 + lane] = acc;
}

// ---------------- SGEMM tiles: C[128 x 128], K=128, chunks of 32 ------------
#define AL 132
#define WL 132

__device__ __forceinline__ void load_chunk(const float* __restrict__ A,
                                           const float* __restrict__ W,
                                           float* As, float* Ws,
                                           int rowbase, int kc, int t) {
    const float4* A4 = (const float4*)A;
    const float4* W4 = (const float4*)W;
    int kq4 = kc >> 2;
#pragma unroll
    for (int r = 0; r < 4; r++) {
        int idx = t + 256 * r;      // 0..1023
        int m = idx >> 3;           // 0..127
        int kq = idx & 7;           // float4 index within chunk
        int row = rowbase + m;
        float4 v = make_float4(0.f, 0.f, 0.f, 0.f);
        if (row < NN) v = A4[row * 32 + kq4 + kq];
        As[(kq * 4 + 0) * AL + m] = v.x;
        As[(kq * 4 + 1) * AL + m] = v.y;
        As[(kq * 4 + 2) * AL + m] = v.z;
        As[(kq * 4 + 3) * AL + m] = v.w;
        float4 wv = W4[m * 32 + kq4 + kq];
        Ws[(kq * 4 + 0) * WL + m] = wv.x;
        Ws[(kq * 4 + 1) * WL + m] = wv.y;
        Ws[(kq * 4 + 2) * WL + m] = wv.z;
        Ws[(kq * 4 + 3) * WL + m] = wv.w;
    }
}

__device__ __forceinline__ void gemm_accum(const float* As, const float* Ws,
                                           int m0, int n0, float acc[8][8]) {
#pragma unroll
    for (int k = 0; k < 32; k++) {
        float4 a0 = *(const float4*)&As[k * AL + m0];
        float4 a1 = *(const float4*)&As[k * AL + m0 + 4];
        float4 b0 = *(const float4*)&Ws[k * WL + n0];
        float4 b1 = *(const float4*)&Ws[k * WL + n0 + 4];
        float a[8] = {a0.x, a0.y, a0.z, a0.w, a1.x, a1.y, a1.z, a1.w};
        float b[8] = {b0.x, b0.y, b0.z, b0.w, b1.x, b1.y, b1.z, b1.w};
#pragma unroll
        for (int j = 0; j < 8; j++)
#pragma unroll
            for (int i = 0; i < 8; i++) acc[j][i] = fmaf(a[j], b[i], acc[j][i]);
    }
}

// pass 1: g_t = relu(scale[li] * (g_z @ W1^T) + shift[li])
__global__ void __launch_bounds__(256) gemm1_kernel(const float* __restrict__ W1,
                                                    int li) {
    __shared__ float As[32 * AL];
    __shared__ float Ws[32 * WL];
    int t = threadIdx.x;
    int m0 = (t >> 4) * 8;
    int n0 = (t & 15) * 8;
    int rowbase = blockIdx.x * 128;

    float acc[8][8];
#pragma unroll
    for (int j = 0; j < 8; j++)
#pragma unroll
        for (int i = 0; i < 8; i++) acc[j][i] = 0.f;

    for (int kc = 0; kc < 128; kc += 32) {
        load_chunk(g_z, W1, As, Ws, rowbase, kc, t);
        __syncthreads();
        gemm_accum(As, Ws, m0, n0, acc);
        __syncthreads();
    }

    float sc[8], sh[8];
#pragma unroll
    for (int i = 0; i < 8; i++) {
        sc[i] = g_scale[li * HH + n0 + i];
        sh[i] = g_shift[li * HH + n0 + i];
    }
#pragma unroll
    for (int j = 0; j < 8; j++) {
        int row = rowbase + m0 + j;
        if (row < NN) {
            float o[8];
#pragma unroll
            for (int i = 0; i < 8; i++) o[i] = fmaxf(fmaf(acc[j][i], sc[i], sh[i]), 0.f);
            *(float4*)&g_t[row * 128 + n0]     = make_float4(o[0], o[1], o[2], o[3]);
            *(float4*)&g_t[row * 128 + n0 + 4] = make_float4(o[4], o[5], o[6], o[7]);
        }
    }
}

// pass 2: g_h = relu(g_t @ W2^T + b2) + g_h
__global__ void __launch_bounds__(256) gemm2_kernel(const float* __restrict__ W2,
                                                    const float* __restrict__ b2) {
    __shared__ float As[32 * AL];
    __shared__ float Ws[32 * WL];
    int t = threadIdx.x;
    int m0 = (t >> 4) * 8;
    int n0 = (t & 15) * 8;
    int rowbase = blockIdx.x * 128;

    float acc[8][8];
#pragma unroll
    for (int j = 0; j < 8; j++)
#pragma unroll
        for (int i = 0; i < 8; i++) acc[j][i] = 0.f;

    for (int kc = 0; kc < 128; kc += 32) {
        load_chunk(g_t, W2, As, Ws, rowbase, kc, t);
        __syncthreads();
        gemm_accum(As, Ws, m0, n0, acc);
        __syncthreads();
    }

    float bias[8];
#pragma unroll
    for (int i = 0; i < 8; i++) bias[i] = b2[n0 + i];
#pragma unroll
    for (int j = 0; j < 8; j++) {
        int row = rowbase + m0 + j;
        if (row < NN) {
            float4 h0 = *(const float4*)&g_h[row * 128 + n0];
            float4 h1 = *(const float4*)&g_h[row * 128 + n0 + 4];
            float4 o0, o1;
            o0.x = fmaxf(acc[j][0] + bias[0], 0.f) + h0.x;
            o0.y = fmaxf(acc[j][1] + bias[1], 0.f) + h0.y;
            o0.z = fmaxf(acc[j][2] + bias[2], 0.f) + h0.z;
            o0.w = fmaxf(acc[j][3] + bias[3], 0.f) + h0.w;
            o1.x = fmaxf(acc[j][4] + bias[4], 0.f) + h1.x;
            o1.y = fmaxf(acc[j][5] + bias[5], 0.f) + h1.y;
            o1.z = fmaxf(acc[j][6] + bias[6], 0.f) + h1.z;
            o1.w = fmaxf(acc[j][7] + bias[7], 0.f) + h1.w;
            *(float4*)&g_h[row * 128 + n0]     = o0;
            *(float4*)&g_h[row * 128 + n0 + 4] = o1;
        }
    }
}

// ---------------- pooling (batch_idx sorted -> run-length accumulation) -----
__global__ void __launch_bounds__(128) pool_kernel(const int* __restrict__ batch) {
    int t = threadIdx.x;            // 128
    int base = blockIdx.x * 128;
    float acc = 0.f, runc = 0.f;
    int cur = -1;
    for (int j = 0; j < 128; j++) {
        int node = base + j;
        if (node >= NN) break;
        int g = batch[node];
        if (g != cur) {
            if (cur >= 0) {
                atomicAdd(&g_pool[cur * 128 + t], acc);
                if (t == 0) atomicAdd(&g_gcnt[cur], runc);
            }
            cur = g; acc = 0.f; runc = 0.f;
        }
        acc += g_h[node * 128 + t];
        runc += 1.f;
    }
    if (cur >= 0) {
        atomicAdd(&g_pool[cur * 128 + t], acc);
        if (t == 0) atomicAdd(&g_gcnt[cur], runc);
    }
}

// ---------------- final projection ------------------------------------------
__global__ void __launch_bounds__(128) proj_kernel(const float* __restrict__ pW,
                                                   const float* __restrict__ pb,
                                                   float* __restrict__ out) {
    __shared__ float pr[128];
    int g = blockIdx.x, t = threadIdx.x;
    float c = fmaxf(g_gcnt[g], 1.f);
    pr[t] = g_pool[g * 128 + t] / c;
    __syncthreads();
    float acc = pb[t];
#pragma unroll 4
    for (int h = 0; h < 128; h++) acc = fmaf(pr[h], pW[t * 128 + h], acc);
    out[g * 128 + t] = acc;
}

// ---------------- launch ------------------------------------------------------
extern "C" void kernel_launch(void* const* d_in, const int* in_sizes, int n_in,
                              void* d_out, int out_size) {
    const float* x       = (const float*)d_in[0];
    const int*   ei      = (const int*)  d_in[1];
    const float* ea      = (const float*)d_in[2];
    const int*   batch   = (const int*)  d_in[3];
    const float* node_W  = (const float*)d_in[4];
    const float* node_b  = (const float*)d_in[5];
    const float* edge_W  = (const float*)d_in[6];
    const float* edge_b  = (const float*)d_in[7];
    const float* lin1_W  = (const float*)d_in[8];
    const float* lin1_b  = (const float*)d_in[9];
    const float* bn_g    = (const float*)d_in[10];
    const float* bn_b    = (const float*)d_in[11];
    const float* bn_m    = (const float*)d_in[12];
    const float* bn_v    = (const float*)d_in[13];
    const float* lin2_W  = (const float*)d_in[14];
    const float* lin2_b  = (const float*)d_in[15];
    const float* proj_W  = (const float*)d_in[16];
    const float* proj_b  = (const float*)d_in[17];
    float* out = (float*)d_out;

    zero_kernel<<<(NN + 255) / 256, 256>>>();
    prep_kernel<<<(NL * HH + 127) / 128, 128>>>(lin1_b, bn_g, bn_b, bn_m, bn_v);
    node_embed<<<(NN + 31) / 32, 128>>>(x, node_W, node_b);
    hist_kernel<<<(NE + 255) / 256, 256>>>(ei);
    scan_kernel<<<1, 1024>>>();
    scatter_kernel<<<(NE + 255) / 256, 256>>>(ei, ea);

    const int gemm_grid = (NN + 127) / 128;
    for (int li = 0; li < NL; li++) {
        aggregate_kernel<<<(NN * 32 + 255) / 256, 256>>>(edge_W, edge_b);
        gemm1_kernel<<<gemm_grid, 256>>>(lin1_W + li * HH * HH, li);
        gemm2_kernel<<<gemm_grid, 256>>>(lin2_W + li * HH * HH, lin2_b + li * HH);
    }

    pool_kernel<<<(NN + 127) / 128, 128>>>(batch);
    proj_kernel<<<NG, 128>>>(proj_W, proj_b, out);
}